// round 16
// baseline (speedup 1.0000x reference)
#include <cuda_runtime.h>
#include <cuda_fp16.h>

#define H 64
#define NMAX 50000
#define EMAX 800000
#define MAXTILE 96

typedef unsigned long long u64;

// ---- static scratch (no allocations allowed) ----
__device__ float    g_hw0[NMAX * H];     // hw fp32 ping (self terms, exact)
__device__ float    g_hw1[NMAX * H];     // hw fp32 pong
__device__ unsigned g_hw16a[NMAX * 32];  // hw fp16 mirror ping (gather traffic)
__device__ unsigned g_hw16b[NMAX * 32];  // hw fp16 mirror pong
__device__ float    g_dinv[NMAX];
__device__ int      g_cnt[NMAX];         // zero-init; self-cleared each call
__device__ int      g_off[NMAX + 1];
__device__ int      g_cur[NMAX];
__device__ int      g_csr[EMAX];
__device__ int      g_part[2048];

// ---- software grid barrier (self-resetting; zero-init) ----
__device__ volatile unsigned g_arr[16];
__device__ volatile unsigned g_dep[16];

__device__ __forceinline__ void gsync(int p, unsigned nb) {
    __syncthreads();
    if (threadIdx.x == 0) {
        __threadfence();
        atomicAdd((unsigned*)&g_arr[p], 1u);
        while (g_arr[p] < nb) __nanosleep(64);
        __threadfence();
        unsigned d = atomicAdd((unsigned*)&g_dep[p], 1u) + 1;
        if (d == nb) {
            g_arr[p] = 0;
            __threadfence();
            g_dep[p] = 0;
        }
    }
    __syncthreads();
}

// packed f32x2 helpers
__device__ __forceinline__ void ffma2(u64& d, u64 a, u64 b) {
    asm("fma.rn.f32x2 %0, %1, %2, %3;" : "=l"(d) : "l"(a), "l"(b), "l"(d));
}
__device__ __forceinline__ u64 pack2(float v) {
    u64 r; unsigned u = __float_as_uint(v);
    asm("mov.b64 %0, {%1, %1};" : "=l"(r) : "r"(u));
    return r;
}
__device__ __forceinline__ u64 packf(float lo, float hi) {
    u64 r;
    asm("mov.b64 %0, {%1, %2};" : "=l"(r) : "f"(lo), "f"(hi));
    return r;
}
__device__ __forceinline__ void unpackf(u64 v, float& lo, float& hi) {
    asm("mov.b64 {%0, %1}, %2;" : "=f"(lo), "=f"(hi) : "l"(v));
}
union F4U2 { float4 f; u64 u[2]; };

// accumulate 8 halves (one uint4) into 8 fp32 accumulators
__device__ __forceinline__ void h2acc8(float* acc, uint4 v) {
    float2 a = __half22float2(*(__half2*)&v.x);
    float2 b = __half22float2(*(__half2*)&v.y);
    float2 c = __half22float2(*(__half2*)&v.z);
    float2 d = __half22float2(*(__half2*)&v.w);
    acc[0] += a.x; acc[1] += a.y; acc[2] += b.x; acc[3] += b.y;
    acc[4] += c.x; acc[5] += c.y; acc[6] += d.x; acc[7] += d.y;
}

// block-wide exclusive scan (256 thr); sS = 32-int scratch
__device__ __forceinline__ int block_excl_scan(int v, int* sS, int* total) {
    int t = threadIdx.x, lane = t & 31, w = t >> 5;
    int x = v;
#pragma unroll
    for (int o = 1; o < 32; o <<= 1) {
        int y = __shfl_up_sync(0xffffffffu, x, o);
        if (lane >= o) x += y;
    }
    if (lane == 31) sS[w] = x;
    __syncthreads();
    if (w == 0) {
        int s = (lane < 8) ? sS[lane] : 0;
#pragma unroll
        for (int o = 1; o < 8; o <<= 1) {
            int y = __shfl_up_sync(0xffffffffu, s, o);
            if (lane >= o) s += y;
        }
        if (lane < 8) sS[lane] = s;
    }
    __syncthreads();
    int pref = (w > 0) ? sS[w - 1] : 0;
    if (total) *total = sS[7];
    int r = pref + x - v;
    __syncthreads();
    return r;
}

// ---- 8-lane pull aggregate, MLP-8: lane j8 owns cols [8*j8, 8*j8+8) ----
__device__ __forceinline__ void agg_node16_8(
    const float* __restrict__ hwSelf, const unsigned* __restrict__ hw16,
    int i, int j8, float* __restrict__ o /*8 floats*/)
{
    int cu = j8 * 4;                  // uint index within 32-uint fp16 row
    float acc[8];
    {
        const float4* sp = (const float4*)&hwSelf[i * 64 + j8 * 8];
        float4 a0 = sp[0], a1 = sp[1];
        acc[0] = a0.x; acc[1] = a0.y; acc[2] = a0.z; acc[3] = a0.w;
        acc[4] = a1.x; acc[5] = a1.y; acc[6] = a1.z; acc[7] = a1.w;
    }
    int j = g_off[i];
    int end = g_off[i + 1];

    while (j + 8 <= end) {
        int s0 = g_csr[j+0], s1 = g_csr[j+1], s2 = g_csr[j+2], s3 = g_csr[j+3];
        int s4 = g_csr[j+4], s5 = g_csr[j+5], s6 = g_csr[j+6], s7 = g_csr[j+7];
        uint4 v0 = __ldcg((const uint4*)&hw16[s0 * 32 + cu]);
        uint4 v1 = __ldcg((const uint4*)&hw16[s1 * 32 + cu]);
        uint4 v2 = __ldcg((const uint4*)&hw16[s2 * 32 + cu]);
        uint4 v3 = __ldcg((const uint4*)&hw16[s3 * 32 + cu]);
        uint4 v4 = __ldcg((const uint4*)&hw16[s4 * 32 + cu]);
        uint4 v5 = __ldcg((const uint4*)&hw16[s5 * 32 + cu]);
        uint4 v6 = __ldcg((const uint4*)&hw16[s6 * 32 + cu]);
        uint4 v7 = __ldcg((const uint4*)&hw16[s7 * 32 + cu]);
        h2acc8(acc, v0); h2acc8(acc, v1); h2acc8(acc, v2); h2acc8(acc, v3);
        h2acc8(acc, v4); h2acc8(acc, v5); h2acc8(acc, v6); h2acc8(acc, v7);
        j += 8;
    }
    if (j + 4 <= end) {
        int s0 = g_csr[j+0], s1 = g_csr[j+1], s2 = g_csr[j+2], s3 = g_csr[j+3];
        uint4 v0 = __ldcg((const uint4*)&hw16[s0 * 32 + cu]);
        uint4 v1 = __ldcg((const uint4*)&hw16[s1 * 32 + cu]);
        uint4 v2 = __ldcg((const uint4*)&hw16[s2 * 32 + cu]);
        uint4 v3 = __ldcg((const uint4*)&hw16[s3 * 32 + cu]);
        h2acc8(acc, v0); h2acc8(acc, v1); h2acc8(acc, v2); h2acc8(acc, v3);
        j += 4;
    }
    if (j + 2 <= end) {
        int s0 = g_csr[j], s1 = g_csr[j+1];
        uint4 v0 = __ldcg((const uint4*)&hw16[s0 * 32 + cu]);
        uint4 v1 = __ldcg((const uint4*)&hw16[s1 * 32 + cu]);
        h2acc8(acc, v0); h2acc8(acc, v1);
        j += 2;
    }
    if (j < end) {
        uint4 v0 = __ldcg((const uint4*)&hw16[g_csr[j] * 32 + cu]);
        h2acc8(acc, v0);
    }

    float dv = g_dinv[i];
#pragma unroll
    for (int r = 0; r < 8; r++) o[r] = acc[r] * dv;
}

// ---- gemm from smem tile -> hwOut fp32 + hw16Out fp16 mirror ----
__device__ __forceinline__ void gemm_from_smem(
    const float* __restrict__ W, float* __restrict__ hwOut,
    unsigned* __restrict__ hw16Out,
    int lo, int tileN, int N, const float* sIn)
{
    int t = threadIdx.x;
    int q  = t & 3;
    int np = t >> 2;
    int na = 2 * np, nb2 = na + 1;
    if (na >= tileN) return;          // tileN even -> nb2 < tileN too

    u64 acc0[8], acc1[8];
#pragma unroll
    for (int j = 0; j < 8; j++) { acc0[j] = 0ull; acc1[j] = 0ull; }

    const float4* __restrict__ Wq = (const float4*)(W + q * 16);
#pragma unroll 8
    for (int k = 0; k < 64; k++) {
        u64 h0 = pack2(sIn[na  * 65 + k]);
        u64 h1 = pack2(sIn[nb2 * 65 + k]);
        const float4* wp = Wq + k * 16;
        F4U2 w0, w1, w2, w3;
        w0.f = __ldg(wp);     w1.f = __ldg(wp + 1);
        w2.f = __ldg(wp + 2); w3.f = __ldg(wp + 3);
        ffma2(acc0[0], h0, w0.u[0]); ffma2(acc0[1], h0, w0.u[1]);
        ffma2(acc0[2], h0, w1.u[0]); ffma2(acc0[3], h0, w1.u[1]);
        ffma2(acc0[4], h0, w2.u[0]); ffma2(acc0[5], h0, w2.u[1]);
        ffma2(acc0[6], h0, w3.u[0]); ffma2(acc0[7], h0, w3.u[1]);
        ffma2(acc1[0], h1, w0.u[0]); ffma2(acc1[1], h1, w0.u[1]);
        ffma2(acc1[2], h1, w1.u[0]); ffma2(acc1[3], h1, w1.u[1]);
        ffma2(acc1[4], h1, w2.u[0]); ffma2(acc1[5], h1, w2.u[1]);
        ffma2(acc1[6], h1, w3.u[0]); ffma2(acc1[7], h1, w3.u[1]);
    }

    int ia = lo + na;
    int ib = lo + nb2;
    if (ia < N) {
        float da = g_dinv[ia];
        float* p = &hwOut[ia * 64 + q * 16];
        unsigned* p16 = &hw16Out[ia * 32 + q * 8];
#pragma unroll
        for (int r = 0; r < 4; r++) {
            F4U2 o; o.u[0] = acc0[2*r]; o.u[1] = acc0[2*r+1];
            o.f.x *= da; o.f.y *= da; o.f.z *= da; o.f.w *= da;
            *(float4*)&p[r * 4] = o.f;
            __half2 ha = __floats2half2_rn(o.f.x, o.f.y);
            __half2 hb = __floats2half2_rn(o.f.z, o.f.w);
            uint2 u2; u2.x = *(unsigned*)&ha; u2.y = *(unsigned*)&hb;
            *(uint2*)&p16[r * 2] = u2;
        }
    }
    if (ib < N) {
        float db = g_dinv[ib];
        float* p = &hwOut[ib * 64 + q * 16];
        unsigned* p16 = &hw16Out[ib * 32 + q * 8];
#pragma unroll
        for (int r = 0; r < 4; r++) {
            F4U2 o; o.u[0] = acc1[2*r]; o.u[1] = acc1[2*r+1];
            o.f.x *= db; o.f.y *= db; o.f.z *= db; o.f.w *= db;
            *(float4*)&p[r * 4] = o.f;
            __half2 ha = __floats2half2_rn(o.f.x, o.f.y);
            __half2 hb = __floats2half2_rn(o.f.z, o.f.w);
            uint2 u2; u2.x = *(unsigned*)&ha; u2.y = *(unsigned*)&hb;
            *(uint2*)&p16[r * 2] = u2;
        }
    }
}

// =================== persistent megakernel ===================
__global__ void __launch_bounds__(256, 4) persistent_k(
    const float* __restrict__ x, const int* __restrict__ src,
    const int* __restrict__ dst,
    const float* __restrict__ W_enc, const float* __restrict__ b_enc,
    const float* __restrict__ conv_W, const float* __restrict__ conv_b,
    const float* __restrict__ Wd1, const float* __restrict__ bd1,
    const float* __restrict__ Wd2, const float* __restrict__ bd2,
    const float* __restrict__ Wi1, const float* __restrict__ bi1,
    const float* __restrict__ Wi2, const float* __restrict__ bi2,
    float* __restrict__ out, int N, int E, int nb, int tileN)
{
    __shared__ float sBuf[MAXTILE * 65 + 416];  // tile | enc weights | scan
    float* sEnc  = &sBuf[MAXTILE * 65];         // 320
    float* sEncB = &sBuf[MAXTILE * 65 + 320];   // 64
    int*   sS    = (int*)&sBuf[MAXTILE * 65 + 384];

    int t = threadIdx.x;
    int bid = blockIdx.x;
    unsigned T = (unsigned)nb * 256u;
    unsigned gid = (unsigned)bid * 256u + (unsigned)t;

    // ---------- P0: degree histogram ----------
    for (unsigned e = gid; e < (unsigned)E; e += T)
        atomicAdd(&g_cnt[dst[e]], 1);
    gsync(0, nb);

    // ---------- P1: per-block chunk sums ----------
    int chunk = (N + nb - 1) / nb;
    int slo = bid * chunk;
    int shi = min(N, slo + chunk);
    {
        int s = 0;
        for (int i = slo + t; i < shi; i += 256) s += g_cnt[i];
        int tot;
        block_excl_scan(s, sS, &tot);
        if (t == 0) g_part[bid] = tot;
    }
    gsync(1, nb);

    // ---------- P2: block 0 scans the nb partials ----------
    if (bid == 0) {
        int per = (nb + 255) / 256;
        int loc[8];
        int s = 0;
#pragma unroll 8
        for (int r = 0; r < per; r++) {
            int idx = t * per + r;
            int v = (idx < nb) ? g_part[idx] : 0;
            loc[r] = s; s += v;
        }
        int tot;
        int excl = block_excl_scan(s, sS, &tot);
#pragma unroll 8
        for (int r = 0; r < per; r++) {
            int idx = t * per + r;
            if (idx < nb) g_part[idx] = excl + loc[r];
        }
        if (t == 0) g_off[N] = tot;
    }
    gsync(2, nb);

    // ---------- P3: local scan -> off/cur/dinv (+ cnt self-clear) ----------
    {
        int base = g_part[bid];
        int cl = shi - slo;
        int per = (cl + 255) / 256;
        int loc[8], cvals[8];
        int s = 0;
#pragma unroll 8
        for (int r = 0; r < per; r++) {
            int i = slo + t * per + r;
            int v = (t * per + r < cl) ? g_cnt[i] : 0;
            cvals[r] = v; loc[r] = s; s += v;
        }
        int excl = block_excl_scan(s, sS, nullptr) + base;
#pragma unroll 8
        for (int r = 0; r < per; r++) {
            int i = slo + t * per + r;
            if (t * per + r < cl) {
                int off = excl + loc[r];
                g_cnt[i] = 0;
                g_off[i] = off;
                g_cur[i] = off;
                g_dinv[i] = rsqrtf(1.0f + (float)cvals[r]);
            }
        }
    }
    gsync(3, nb);

    // ---------- P4: CSR fill + fused encoder+gemm0 (x -> hw0/hw16a) ---------
    {
        for (int i = t; i < 320; i += 256) sEnc[i] = W_enc[i];
        if (t < 64) sEncB[t] = b_enc[t];
        for (unsigned e = gid; e < (unsigned)E; e += T) {
            int s = src[e];
            int c = dst[e];
            int pos = atomicAdd(&g_cur[c], 1);
            g_csr[pos] = s;
        }
        __syncthreads();

        int c4 = (t & 15) * 4;
        float we[20], be[4];
#pragma unroll
        for (int f = 0; f < 5; f++)
#pragma unroll
            for (int j = 0; j < 4; j++) we[f * 4 + j] = sEnc[f * 64 + c4 + j];
#pragma unroll
        for (int j = 0; j < 4; j++) be[j] = sEncB[c4 + j];

        for (int tile = bid; tile * tileN < N; tile += nb) {
            int lo = tile * tileN;
            __syncthreads();
            for (int s = t; s < tileN * 16; s += 256) {
                int n = s >> 4;
                int i = lo + n;
                float a0 = 0.f, a1 = 0.f, a2 = 0.f, a3 = 0.f;
                if (i < N) {
                    a0 = be[0]; a1 = be[1]; a2 = be[2]; a3 = be[3];
#pragma unroll
                    for (int f = 0; f < 5; f++) {
                        float xv = x[i * 5 + f];
                        a0 += xv * we[f * 4 + 0];
                        a1 += xv * we[f * 4 + 1];
                        a2 += xv * we[f * 4 + 2];
                        a3 += xv * we[f * 4 + 3];
                    }
                    a0 = fmaxf(a0, 0.f); a1 = fmaxf(a1, 0.f);
                    a2 = fmaxf(a2, 0.f); a3 = fmaxf(a3, 0.f);
                }
                float* sp = &sBuf[n * 65 + c4];
                sp[0] = a0; sp[1] = a1; sp[2] = a2; sp[3] = a3;
            }
            __syncthreads();
            gemm_from_smem(conv_W, g_hw0, g_hw16a, lo, tileN, N, sBuf);
        }
    }
    gsync(4, nb);

    // ---------- P5: agg(hw0/16a)+gemm1 -> hw1/16b (8-lane agg slots) --------
    for (int tile = bid; tile * tileN < N; tile += nb) {
        int lo = tile * tileN;
        __syncthreads();
        for (int s = t; s < tileN * 8; s += 256) {
            int n = s >> 3;
            int j8 = s & 7;
            int i = lo + n;
            float o[8] = {0.f, 0.f, 0.f, 0.f, 0.f, 0.f, 0.f, 0.f};
            if (i < N) {
                agg_node16_8(g_hw0, g_hw16a, i, j8, o);
#pragma unroll
                for (int r = 0; r < 8; r++)
                    o[r] = fmaxf(o[r] + conv_b[j8 * 8 + r], 0.f);
            }
            float* sp = &sBuf[n * 65 + j8 * 8];
#pragma unroll
            for (int r = 0; r < 8; r++) sp[r] = o[r];
        }
        __syncthreads();
        gemm_from_smem(conv_W + 4096, g_hw1, g_hw16b, lo, tileN, N, sBuf);
    }
    gsync(5, nb);

    // ---------- P6: agg(hw1/16b)+gemm2 -> hw0/16a ----------
    for (int tile = bid; tile * tileN < N; tile += nb) {
        int lo = tile * tileN;
        __syncthreads();
        for (int s = t; s < tileN * 8; s += 256) {
            int n = s >> 3;
            int j8 = s & 7;
            int i = lo + n;
            float o[8] = {0.f, 0.f, 0.f, 0.f, 0.f, 0.f, 0.f, 0.f};
            if (i < N) {
                agg_node16_8(g_hw1, g_hw16b, i, j8, o);
#pragma unroll
                for (int r = 0; r < 8; r++)
                    o[r] = fmaxf(o[r] + conv_b[64 + j8 * 8 + r], 0.f);
            }
            float* sp = &sBuf[n * 65 + j8 * 8];
#pragma unroll
            for (int r = 0; r < 8; r++) sp[r] = o[r];
        }
        __syncthreads();
        gemm_from_smem(conv_W + 8192, g_hw0, g_hw16a, lo, tileN, N, sBuf);
    }
    gsync(6, nb);

    // ---------- P7: agg(hw0/16a) + heads, 4 nodes/warp ----------
    {
        u64*   sWdi = (u64*)&sBuf[0];      // 2048 u64 = [0..4096)
        u64*   sbdi = (u64*)&sBuf[4096];   // 32 u64
        float* sWd2 = &sBuf[4160];
        float* sWi2 = &sBuf[4192];
        float* scb  = &sBuf[4224];         // 64
        float* sh   = &sBuf[4288];         // 8 warps * 4 nodes * 64 = 2048

        for (int idx = t; idx < 2048; idx += 256)
            sWdi[idx] = packf(Wd1[idx], Wi1[idx]);
        if (t < 32) {
            sbdi[t] = packf(bd1[t], bi1[t]);
            sWd2[t] = Wd2[t];
            sWi2[t] = Wi2[t];
        }
        if (t < 64) scb[t] = conv_b[128 + t];
        __syncthreads();

        int w = t >> 5, lane = t & 31;
        int nw = lane >> 3;       // node slot 0..3
        int j8 = lane & 7;
        float bd2v = bd2[0], bi2v = bi2[0];
        float* shw = &sh[w * 256];

        for (int tile = bid; tile * tileN < N; tile += nb) {
            int lo = tile * tileN;
            int hiN = min(N, lo + tileN);
            for (int base = lo; base < hiN; base += 32) {
                int i = base + w * 4 + nw;
                float o[8] = {0.f, 0.f, 0.f, 0.f, 0.f, 0.f, 0.f, 0.f};
                bool valid = (i < hiN);
                if (valid) {
                    agg_node16_8(g_hw0, g_hw16a, i, j8, o);
#pragma unroll
                    for (int r = 0; r < 8; r++)
                        o[r] = fmaxf(o[r] + scb[j8 * 8 + r], 0.f);
                }
                float* sp = &shw[nw * 64 + j8 * 8];
#pragma unroll
                for (int r = 0; r < 8; r++) sp[r] = valid ? o[r] : 0.f;
                __syncwarp();

                u64 acc[4];
#pragma unroll
                for (int m = 0; m < 4; m++) acc[m] = sbdi[lane];
#pragma unroll 8
                for (int k = 0; k < 64; k++) {
                    u64 wdi = sWdi[k * 32 + lane];
                    ffma2(acc[0], pack2(shw[k]),        wdi);
                    ffma2(acc[1], pack2(shw[64 + k]),   wdi);
                    ffma2(acc[2], pack2(shw[128 + k]),  wdi);
                    ffma2(acc[3], pack2(shw[192 + k]),  wdi);
                }
                float vd[4], vi[4];
#pragma unroll
                for (int m = 0; m < 4; m++) {
                    float ad, ai;
                    unpackf(acc[m], ad, ai);
                    vd[m] = fmaxf(ad, 0.f) * sWd2[lane];
                    vi[m] = fmaxf(ai, 0.f) * sWi2[lane];
                }
#pragma unroll
                for (int o2 = 16; o2 > 0; o2 >>= 1) {
#pragma unroll
                    for (int m = 0; m < 4; m++) {
                        vd[m] += __shfl_xor_sync(0xffffffffu, vd[m], o2);
                        vi[m] += __shfl_xor_sync(0xffffffffu, vi[m], o2);
                    }
                }
                if (lane == 0) {
#pragma unroll
                    for (int m = 0; m < 4; m++) {
                        int io = base + w * 4 + m;
                        if (io < hiN) {
                            out[io]     = vd[m] + bd2v;
                            out[N + io] = vi[m] + bi2v;
                        }
                    }
                }
                __syncwarp();
            }
        }
    }
}

// ---------------- launch ----------------
extern "C" void kernel_launch(void* const* d_in, const int* in_sizes, int n_in,
                              void* d_out, int out_size)
{
    const float* x      = (const float*)d_in[0];
    const int*   ei     = (const int*)d_in[1];     // int32 (JAX x64 off)
    const float* W_enc  = (const float*)d_in[2];
    const float* b_enc  = (const float*)d_in[3];
    const float* conv_W = (const float*)d_in[4];
    const float* conv_b = (const float*)d_in[5];
    const float* W_d1   = (const float*)d_in[6];
    const float* b_d1   = (const float*)d_in[7];
    const float* W_d2   = (const float*)d_in[8];
    const float* b_d2   = (const float*)d_in[9];
    const float* W_i1   = (const float*)d_in[10];
    const float* b_i1   = (const float*)d_in[11];
    const float* W_i2   = (const float*)d_in[12];
    const float* b_i2   = (const float*)d_in[13];
    float* out = (float*)d_out;

    int N = in_sizes[0] / 5;
    int E = in_sizes[1] / 2;
    const int* src = ei;
    const int* dst = ei + E;

    int dev = 0;
    cudaGetDevice(&dev);
    int sms = 148;
    cudaDeviceGetAttribute(&sms, cudaDevAttrMultiProcessorCount, dev);
    int bpm = 0;
    cudaOccupancyMaxActiveBlocksPerMultiprocessor(&bpm, persistent_k, 256, 0);
    if (bpm < 1) bpm = 1;
    if (bpm > 4) bpm = 4;
    int nb = sms * bpm;
    if (nb > 2048) nb = 2048;

    // exact partition: one tile per block (rounded even, capped by smem)
    int tileN = (N + nb - 1) / nb;
    tileN = (tileN + 1) & ~1;
    if (tileN < 2) tileN = 2;
    if (tileN > MAXTILE) tileN = MAXTILE;   // fallback loop handles leftovers

    persistent_k<<<nb, 256>>>(x, src, dst, W_enc, b_enc, conv_W, conv_b,
                              W_d1, b_d1, W_d2, b_d2,
                              W_i1, b_i1, W_i2, b_i2,
                              out, N, E, nb, tileN);
}

// round 17
// speedup vs baseline: 1.1093x; 1.1093x over previous
#include <cuda_runtime.h>
#include <cuda_fp16.h>

#define H 64
#define NMAX 50000
#define EMAX 800000
#define MAXTILE 96

typedef unsigned long long u64;

// ---- static scratch (no allocations allowed) ----
__device__ unsigned g_hw16a[NMAX * 32];  // hw fp16 ping (only representation)
__device__ unsigned g_hw16b[NMAX * 32];  // hw fp16 pong
__device__ float    g_dinv[NMAX];
__device__ int      g_cnt[NMAX];         // zero-init; self-cleared each call
__device__ int      g_off[NMAX + 1];
__device__ int      g_cur[NMAX];
__device__ int      g_csr[EMAX];
__device__ int      g_part[2048];

// ---- software grid barrier (self-resetting; zero-init) ----
__device__ volatile unsigned g_arr[16];
__device__ volatile unsigned g_dep[16];

__device__ __forceinline__ void gsync(int p, unsigned nb) {
    __syncthreads();
    if (threadIdx.x == 0) {
        __threadfence();
        atomicAdd((unsigned*)&g_arr[p], 1u);
        while (g_arr[p] < nb) __nanosleep(64);
        __threadfence();
        unsigned d = atomicAdd((unsigned*)&g_dep[p], 1u) + 1;
        if (d == nb) {
            g_arr[p] = 0;
            __threadfence();
            g_dep[p] = 0;
        }
    }
    __syncthreads();
}

// packed f32x2 helpers
__device__ __forceinline__ void ffma2(u64& d, u64 a, u64 b) {
    asm("fma.rn.f32x2 %0, %1, %2, %3;" : "=l"(d) : "l"(a), "l"(b), "l"(d));
}
__device__ __forceinline__ u64 pack2(float v) {
    u64 r; unsigned u = __float_as_uint(v);
    asm("mov.b64 %0, {%1, %1};" : "=l"(r) : "r"(u));
    return r;
}
__device__ __forceinline__ u64 packf(float lo, float hi) {
    u64 r;
    asm("mov.b64 %0, {%1, %2};" : "=l"(r) : "f"(lo), "f"(hi));
    return r;
}
__device__ __forceinline__ void unpackf(u64 v, float& lo, float& hi) {
    asm("mov.b64 {%0, %1}, %2;" : "=f"(lo), "=f"(hi) : "l"(v));
}
union F4U2 { float4 f; u64 u[2]; };

// accumulate 8 halves (one uint4) into 8 fp32 accumulators
__device__ __forceinline__ void h2acc8(float* acc, uint4 v) {
    float2 a = __half22float2(*(__half2*)&v.x);
    float2 b = __half22float2(*(__half2*)&v.y);
    float2 c = __half22float2(*(__half2*)&v.z);
    float2 d = __half22float2(*(__half2*)&v.w);
    acc[0] += a.x; acc[1] += a.y; acc[2] += b.x; acc[3] += b.y;
    acc[4] += c.x; acc[5] += c.y; acc[6] += d.x; acc[7] += d.y;
}

// block-wide exclusive scan (256 thr); sS = 32-int scratch
__device__ __forceinline__ int block_excl_scan(int v, int* sS, int* total) {
    int t = threadIdx.x, lane = t & 31, w = t >> 5;
    int x = v;
#pragma unroll
    for (int o = 1; o < 32; o <<= 1) {
        int y = __shfl_up_sync(0xffffffffu, x, o);
        if (lane >= o) x += y;
    }
    if (lane == 31) sS[w] = x;
    __syncthreads();
    if (w == 0) {
        int s = (lane < 8) ? sS[lane] : 0;
#pragma unroll
        for (int o = 1; o < 8; o <<= 1) {
            int y = __shfl_up_sync(0xffffffffu, s, o);
            if (lane >= o) s += y;
        }
        if (lane < 8) sS[lane] = s;
    }
    __syncthreads();
    int pref = (w > 0) ? sS[w - 1] : 0;
    if (total) *total = sS[7];
    int r = pref + x - v;
    __syncthreads();
    return r;
}

// ---- 8-lane pull aggregate (MLP-4): lane j8 owns cols [8*j8, 8*j8+8) ----
// fp16 LDG.128 gathers incl. self term; fp32 accumulation.
__device__ __forceinline__ void agg_node16_8(
    const unsigned* __restrict__ hw16, int i, int j8,
    float* __restrict__ o /*8 floats*/)
{
    int cu = j8 * 4;                  // uint index within 32-uint fp16 row
    float acc[8];
    {
        uint4 sv = *(const uint4*)&hw16[i * 32 + cu];   // self (L1-cacheable)
        float2 a = __half22float2(*(__half2*)&sv.x);
        float2 b = __half22float2(*(__half2*)&sv.y);
        float2 c = __half22float2(*(__half2*)&sv.z);
        float2 d = __half22float2(*(__half2*)&sv.w);
        acc[0] = a.x; acc[1] = a.y; acc[2] = b.x; acc[3] = b.y;
        acc[4] = c.x; acc[5] = c.y; acc[6] = d.x; acc[7] = d.y;
    }
    int j = g_off[i];
    int end = g_off[i + 1];

    while (j + 4 <= end) {
        int s0 = g_csr[j+0], s1 = g_csr[j+1], s2 = g_csr[j+2], s3 = g_csr[j+3];
        uint4 v0 = __ldcg((const uint4*)&hw16[s0 * 32 + cu]);
        uint4 v1 = __ldcg((const uint4*)&hw16[s1 * 32 + cu]);
        uint4 v2 = __ldcg((const uint4*)&hw16[s2 * 32 + cu]);
        uint4 v3 = __ldcg((const uint4*)&hw16[s3 * 32 + cu]);
        h2acc8(acc, v0); h2acc8(acc, v1); h2acc8(acc, v2); h2acc8(acc, v3);
        j += 4;
    }
    if (j + 2 <= end) {
        int s0 = g_csr[j], s1 = g_csr[j+1];
        uint4 v0 = __ldcg((const uint4*)&hw16[s0 * 32 + cu]);
        uint4 v1 = __ldcg((const uint4*)&hw16[s1 * 32 + cu]);
        h2acc8(acc, v0); h2acc8(acc, v1);
        j += 2;
    }
    if (j < end) {
        uint4 v0 = __ldcg((const uint4*)&hw16[g_csr[j] * 32 + cu]);
        h2acc8(acc, v0);
    }

    float dv = g_dinv[i];
#pragma unroll
    for (int r = 0; r < 8; r++) o[r] = acc[r] * dv;
}

// ---- gemm from smem tile -> fp16 mirror only ----
__device__ __forceinline__ void gemm_from_smem(
    const float* __restrict__ W, unsigned* __restrict__ hw16Out,
    int lo, int tileN, int N, const float* sIn)
{
    int t = threadIdx.x;
    int q  = t & 3;
    int np = t >> 2;
    int na = 2 * np, nb2 = na + 1;
    if (na >= tileN) return;          // tileN even -> nb2 < tileN too

    u64 acc0[8], acc1[8];
#pragma unroll
    for (int j = 0; j < 8; j++) { acc0[j] = 0ull; acc1[j] = 0ull; }

    const float4* __restrict__ Wq = (const float4*)(W + q * 16);
#pragma unroll 8
    for (int k = 0; k < 64; k++) {
        u64 h0 = pack2(sIn[na  * 65 + k]);
        u64 h1 = pack2(sIn[nb2 * 65 + k]);
        const float4* wp = Wq + k * 16;
        F4U2 w0, w1, w2, w3;
        w0.f = __ldg(wp);     w1.f = __ldg(wp + 1);
        w2.f = __ldg(wp + 2); w3.f = __ldg(wp + 3);
        ffma2(acc0[0], h0, w0.u[0]); ffma2(acc0[1], h0, w0.u[1]);
        ffma2(acc0[2], h0, w1.u[0]); ffma2(acc0[3], h0, w1.u[1]);
        ffma2(acc0[4], h0, w2.u[0]); ffma2(acc0[5], h0, w2.u[1]);
        ffma2(acc0[6], h0, w3.u[0]); ffma2(acc0[7], h0, w3.u[1]);
        ffma2(acc1[0], h1, w0.u[0]); ffma2(acc1[1], h1, w0.u[1]);
        ffma2(acc1[2], h1, w1.u[0]); ffma2(acc1[3], h1, w1.u[1]);
        ffma2(acc1[4], h1, w2.u[0]); ffma2(acc1[5], h1, w2.u[1]);
        ffma2(acc1[6], h1, w3.u[0]); ffma2(acc1[7], h1, w3.u[1]);
    }

    int ia = lo + na;
    int ib = lo + nb2;
    if (ia < N) {
        float da = g_dinv[ia];
        uint4 u4;
        unsigned* up = (unsigned*)&u4;
#pragma unroll
        for (int r = 0; r < 4; r++) {
            F4U2 o; o.u[0] = acc0[2*r]; o.u[1] = acc0[2*r+1];
            __half2 h = __floats2half2_rn(o.f.x * da, o.f.y * da);
            __half2 g = __floats2half2_rn(o.f.z * da, o.f.w * da);
            up[(r & 1) * 2]     = *(unsigned*)&h;
            up[(r & 1) * 2 + 1] = *(unsigned*)&g;
            if (r & 1) *(uint4*)&hw16Out[ia * 32 + q * 8 + (r >> 1) * 4] = u4;
        }
    }
    if (ib < N) {
        float db = g_dinv[ib];
        uint4 u4;
        unsigned* up = (unsigned*)&u4;
#pragma unroll
        for (int r = 0; r < 4; r++) {
            F4U2 o; o.u[0] = acc1[2*r]; o.u[1] = acc1[2*r+1];
            __half2 h = __floats2half2_rn(o.f.x * db, o.f.y * db);
            __half2 g = __floats2half2_rn(o.f.z * db, o.f.w * db);
            up[(r & 1) * 2]     = *(unsigned*)&h;
            up[(r & 1) * 2 + 1] = *(unsigned*)&g;
            if (r & 1) *(uint4*)&hw16Out[ib * 32 + q * 8 + (r >> 1) * 4] = u4;
        }
    }
}

// =================== persistent megakernel ===================
__global__ void __launch_bounds__(256, 4) persistent_k(
    const float* __restrict__ x, const int* __restrict__ src,
    const int* __restrict__ dst,
    const float* __restrict__ W_enc, const float* __restrict__ b_enc,
    const float* __restrict__ conv_W, const float* __restrict__ conv_b,
    const float* __restrict__ Wd1, const float* __restrict__ bd1,
    const float* __restrict__ Wd2, const float* __restrict__ bd2,
    const float* __restrict__ Wi1, const float* __restrict__ bi1,
    const float* __restrict__ Wi2, const float* __restrict__ bi2,
    float* __restrict__ out, int N, int E, int nb, int tileN)
{
    __shared__ float sBuf[MAXTILE * 65 + 416];  // tile | enc weights | scan
    float* sEnc  = &sBuf[MAXTILE * 65];         // 320
    float* sEncB = &sBuf[MAXTILE * 65 + 320];   // 64
    int*   sS    = (int*)&sBuf[MAXTILE * 65 + 384];

    int t = threadIdx.x;
    int bid = blockIdx.x;
    unsigned T = (unsigned)nb * 256u;
    unsigned gid = (unsigned)bid * 256u + (unsigned)t;

    // ---------- P0: degree histogram ----------
    for (unsigned e = gid; e < (unsigned)E; e += T)
        atomicAdd(&g_cnt[dst[e]], 1);
    gsync(0, nb);

    // ---------- P1: per-block chunk sums ----------
    int chunk = (N + nb - 1) / nb;
    int slo = bid * chunk;
    int shi = min(N, slo + chunk);
    {
        int s = 0;
        for (int i = slo + t; i < shi; i += 256) s += g_cnt[i];
        int tot;
        block_excl_scan(s, sS, &tot);
        if (t == 0) g_part[bid] = tot;
    }
    gsync(1, nb);

    // ---------- P2: block 0 scans the nb partials ----------
    if (bid == 0) {
        int per = (nb + 255) / 256;
        int loc[8];
        int s = 0;
#pragma unroll 8
        for (int r = 0; r < per; r++) {
            int idx = t * per + r;
            int v = (idx < nb) ? g_part[idx] : 0;
            loc[r] = s; s += v;
        }
        int tot;
        int excl = block_excl_scan(s, sS, &tot);
#pragma unroll 8
        for (int r = 0; r < per; r++) {
            int idx = t * per + r;
            if (idx < nb) g_part[idx] = excl + loc[r];
        }
        if (t == 0) g_off[N] = tot;
    }
    gsync(2, nb);

    // ---------- P3: local scan -> off/cur/dinv (+ cnt self-clear) ----------
    {
        int base = g_part[bid];
        int cl = shi - slo;
        int per = (cl + 255) / 256;
        int loc[8], cvals[8];
        int s = 0;
#pragma unroll 8
        for (int r = 0; r < per; r++) {
            int i = slo + t * per + r;
            int v = (t * per + r < cl) ? g_cnt[i] : 0;
            cvals[r] = v; loc[r] = s; s += v;
        }
        int excl = block_excl_scan(s, sS, nullptr) + base;
#pragma unroll 8
        for (int r = 0; r < per; r++) {
            int i = slo + t * per + r;
            if (t * per + r < cl) {
                int off = excl + loc[r];
                g_cnt[i] = 0;
                g_off[i] = off;
                g_cur[i] = off;
                g_dinv[i] = rsqrtf(1.0f + (float)cvals[r]);
            }
        }
    }
    gsync(3, nb);

    // ---------- P4: CSR fill + fused encoder+gemm0 (x -> hw16a) ----------
    {
        for (int i = t; i < 320; i += 256) sEnc[i] = W_enc[i];
        if (t < 64) sEncB[t] = b_enc[t];
        for (unsigned e = gid; e < (unsigned)E; e += T) {
            int s = src[e];
            int c = dst[e];
            int pos = atomicAdd(&g_cur[c], 1);
            g_csr[pos] = s;
        }
        __syncthreads();

        int c4 = (t & 15) * 4;
        float we[20], be[4];
#pragma unroll
        for (int f = 0; f < 5; f++)
#pragma unroll
            for (int j = 0; j < 4; j++) we[f * 4 + j] = sEnc[f * 64 + c4 + j];
#pragma unroll
        for (int j = 0; j < 4; j++) be[j] = sEncB[c4 + j];

        for (int tile = bid; tile * tileN < N; tile += nb) {
            int lo = tile * tileN;
            __syncthreads();
            for (int s = t; s < tileN * 16; s += 256) {
                int n = s >> 4;
                int i = lo + n;
                float a0 = 0.f, a1 = 0.f, a2 = 0.f, a3 = 0.f;
                if (i < N) {
                    a0 = be[0]; a1 = be[1]; a2 = be[2]; a3 = be[3];
#pragma unroll
                    for (int f = 0; f < 5; f++) {
                        float xv = x[i * 5 + f];
                        a0 += xv * we[f * 4 + 0];
                        a1 += xv * we[f * 4 + 1];
                        a2 += xv * we[f * 4 + 2];
                        a3 += xv * we[f * 4 + 3];
                    }
                    a0 = fmaxf(a0, 0.f); a1 = fmaxf(a1, 0.f);
                    a2 = fmaxf(a2, 0.f); a3 = fmaxf(a3, 0.f);
                }
                float* sp = &sBuf[n * 65 + c4];
                sp[0] = a0; sp[1] = a1; sp[2] = a2; sp[3] = a3;
            }
            __syncthreads();
            gemm_from_smem(conv_W, g_hw16a, lo, tileN, N, sBuf);
        }
    }
    gsync(4, nb);

    // ---------- P5: agg(hw16a)+gemm1 -> hw16b (8-lane agg slots) ----------
    for (int tile = bid; tile * tileN < N; tile += nb) {
        int lo = tile * tileN;
        __syncthreads();
        for (int s = t; s < tileN * 8; s += 256) {
            int n = s >> 3;
            int j8 = s & 7;
            int i = lo + n;
            float o[8] = {0.f, 0.f, 0.f, 0.f, 0.f, 0.f, 0.f, 0.f};
            if (i < N) {
                agg_node16_8(g_hw16a, i, j8, o);
#pragma unroll
                for (int r = 0; r < 8; r++)
                    o[r] = fmaxf(o[r] + conv_b[j8 * 8 + r], 0.f);
            }
            float* sp = &sBuf[n * 65 + j8 * 8];
#pragma unroll
            for (int r = 0; r < 8; r++) sp[r] = o[r];
        }
        __syncthreads();
        gemm_from_smem(conv_W + 4096, g_hw16b, lo, tileN, N, sBuf);
    }
    gsync(5, nb);

    // ---------- P6: agg(hw16b)+gemm2 -> hw16a ----------
    for (int tile = bid; tile * tileN < N; tile += nb) {
        int lo = tile * tileN;
        __syncthreads();
        for (int s = t; s < tileN * 8; s += 256) {
            int n = s >> 3;
            int j8 = s & 7;
            int i = lo + n;
            float o[8] = {0.f, 0.f, 0.f, 0.f, 0.f, 0.f, 0.f, 0.f};
            if (i < N) {
                agg_node16_8(g_hw16b, i, j8, o);
#pragma unroll
                for (int r = 0; r < 8; r++)
                    o[r] = fmaxf(o[r] + conv_b[64 + j8 * 8 + r], 0.f);
            }
            float* sp = &sBuf[n * 65 + j8 * 8];
#pragma unroll
            for (int r = 0; r < 8; r++) sp[r] = o[r];
        }
        __syncthreads();
        gemm_from_smem(conv_W + 8192, g_hw16a, lo, tileN, N, sBuf);
    }
    gsync(6, nb);

    // ---------- P7: agg(hw16a) + heads, 4 nodes/warp ----------
    {
        u64*   sWdi = (u64*)&sBuf[0];      // 2048 u64 = [0..4096)
        u64*   sbdi = (u64*)&sBuf[4096];   // 32 u64
        float* sWd2 = &sBuf[4160];
        float* sWi2 = &sBuf[4192];
        float* scb  = &sBuf[4224];         // 64
        float* sh   = &sBuf[4288];         // 8 warps * 4 nodes * 64 = 2048

        for (int idx = t; idx < 2048; idx += 256)
            sWdi[idx] = packf(Wd1[idx], Wi1[idx]);
        if (t < 32) {
            sbdi[t] = packf(bd1[t], bi1[t]);
            sWd2[t] = Wd2[t];
            sWi2[t] = Wi2[t];
        }
        if (t < 64) scb[t] = conv_b[128 + t];
        __syncthreads();

        int w = t >> 5, lane = t & 31;
        int nw = lane >> 3;       // node slot 0..3
        int j8 = lane & 7;
        float bd2v = bd2[0], bi2v = bi2[0];
        float* shw = &sh[w * 256];

        for (int tile = bid; tile * tileN < N; tile += nb) {
            int lo = tile * tileN;
            int hiN = min(N, lo + tileN);
            for (int base = lo; base < hiN; base += 32) {
                int i = base + w * 4 + nw;
                float o[8] = {0.f, 0.f, 0.f, 0.f, 0.f, 0.f, 0.f, 0.f};
                bool valid = (i < hiN);
                if (valid) {
                    agg_node16_8(g_hw16a, i, j8, o);
#pragma unroll
                    for (int r = 0; r < 8; r++)
                        o[r] = fmaxf(o[r] + scb[j8 * 8 + r], 0.f);
                }
                float* sp = &shw[nw * 64 + j8 * 8];
#pragma unroll
                for (int r = 0; r < 8; r++) sp[r] = valid ? o[r] : 0.f;
                __syncwarp();

                u64 acc[4];
#pragma unroll
                for (int m = 0; m < 4; m++) acc[m] = sbdi[lane];
#pragma unroll 8
                for (int k = 0; k < 64; k++) {
                    u64 wdi = sWdi[k * 32 + lane];
                    ffma2(acc[0], pack2(shw[k]),        wdi);
                    ffma2(acc[1], pack2(shw[64 + k]),   wdi);
                    ffma2(acc[2], pack2(shw[128 + k]),  wdi);
                    ffma2(acc[3], pack2(shw[192 + k]),  wdi);
                }
                float vd[4], vi[4];
#pragma unroll
                for (int m = 0; m < 4; m++) {
                    float ad, ai;
                    unpackf(acc[m], ad, ai);
                    vd[m] = fmaxf(ad, 0.f) * sWd2[lane];
                    vi[m] = fmaxf(ai, 0.f) * sWi2[lane];
                }
#pragma unroll
                for (int o2 = 16; o2 > 0; o2 >>= 1) {
#pragma unroll
                    for (int m = 0; m < 4; m++) {
                        vd[m] += __shfl_xor_sync(0xffffffffu, vd[m], o2);
                        vi[m] += __shfl_xor_sync(0xffffffffu, vi[m], o2);
                    }
                }
                if (lane == 0) {
#pragma unroll
                    for (int m = 0; m < 4; m++) {
                        int io = base + w * 4 + m;
                        if (io < hiN) {
                            out[io]     = vd[m] + bd2v;
                            out[N + io] = vi[m] + bi2v;
                        }
                    }
                }
                __syncwarp();
            }
        }
    }
}

// ---------------- launch ----------------
extern "C" void kernel_launch(void* const* d_in, const int* in_sizes, int n_in,
                              void* d_out, int out_size)
{
    const float* x      = (const float*)d_in[0];
    const int*   ei     = (const int*)d_in[1];     // int32 (JAX x64 off)
    const float* W_enc  = (const float*)d_in[2];
    const float* b_enc  = (const float*)d_in[3];
    const float* conv_W = (const float*)d_in[4];
    const float* conv_b = (const float*)d_in[5];
    const float* W_d1   = (const float*)d_in[6];
    const float* b_d1   = (const float*)d_in[7];
    const float* W_d2   = (const float*)d_in[8];
    const float* b_d2   = (const float*)d_in[9];
    const float* W_i1   = (const float*)d_in[10];
    const float* b_i1   = (const float*)d_in[11];
    const float* W_i2   = (const float*)d_in[12];
    const float* b_i2   = (const float*)d_in[13];
    float* out = (float*)d_out;

    int N = in_sizes[0] / 5;
    int E = in_sizes[1] / 2;
    const int* src = ei;
    const int* dst = ei + E;

    int dev = 0;
    cudaGetDevice(&dev);
    int sms = 148;
    cudaDeviceGetAttribute(&sms, cudaDevAttrMultiProcessorCount, dev);
    int bpm = 0;
    cudaOccupancyMaxActiveBlocksPerMultiprocessor(&bpm, persistent_k, 256, 0);
    if (bpm < 1) bpm = 1;
    if (bpm > 4) bpm = 4;
    int nb = sms * bpm;
    if (nb > 2048) nb = 2048;

    // exact partition: one tile per block (rounded even, capped by smem)
    int tileN = (N + nb - 1) / nb;
    tileN = (tileN + 1) & ~1;
    if (tileN < 2) tileN = 2;
    if (tileN > MAXTILE) tileN = MAXTILE;   // fallback loop handles leftovers

    persistent_k<<<nb, 256>>>(x, src, dst, W_enc, b_enc, conv_W, conv_b,
                              W_d1, b_d1, W_d2, b_d2,
                              W_i1, b_i1, W_i2, b_i2,
                              out, N, E, nb, tileN);
}